// round 11
// baseline (speedup 1.0000x reference)
#include <cuda_runtime.h>
#include <cuda_bf16.h>
#include <cstdint>

#define M_ROWS 65536
#define T_LEN  16384
#define RC     128
#define NLAYERS 20

// ---- smem layout for k_layer_mma (bytes) ----
// 64-row CTA, 16k chunks, DOUBLE-buffered A and W, 96KB -> 2 CTAs/SM
#define SM_BF     0
#define SM_BG     512
#define SM_BS     1024
#define SM_BR     1536
#define SM_A      2048
#define A_STR     48          // 16 bf16 (32B) + 16B pad -> conflict-free
#define A_PLANE   3072        // 64 rows * 48
#define A_BUF     6144        // hi + lo
#define SM_W      14336       // SM_A + 2*A_BUF
#define W_PLANE   6144        // 128 rows * 48
#define W_BUF     24576       // 4 planes
#define SM_P      63488       // SM_W + 2*W_BUF
#define P_STR     272         // (128+8) bf16 per row
#define P_PLANE   17408       // 64 rows * 272
#define SM_TOTAL  98304       // SM_P + 2*P_PLANE

// ---------------- device scratch ----------------
__device__ float g_res0[(size_t)M_ROWS * RC];
__device__ float g_res1[(size_t)M_ROWS * RC];
__device__ float g_skipacc[(size_t)M_ROWS * RC];
// pre-split weights: [layer][12 tiles][2 planes][8192 bf16], tile = [128n][64k], k contiguous
__device__ __nv_bfloat16 g_wprep[(size_t)NLAYERS * 12 * 2 * 8192];

static const int H_DIL[NLAYERS] = {1,2,4,8,16,32,64,128,256,512,
                                   1,2,4,8,16,32,64,128,256,512};

// ---------------- helpers ----------------
__device__ __forceinline__ uint32_t smem_u32(const void* p) {
    uint32_t a;
    asm("{ .reg .u64 t; cvta.to.shared.u64 t, %1; cvt.u32.u64 %0, t; }"
        : "=r"(a) : "l"(p));
    return a;
}
#define CP_ASYNC16(dst_u32, src_ptr) \
    asm volatile("cp.async.cg.shared.global [%0], [%1], 16;" \
        :: "r"(dst_u32), "l"(src_ptr) : "memory")
#define CP_COMMIT() asm volatile("cp.async.commit_group;" ::: "memory")
#define CP_WAIT0()  asm volatile("cp.async.wait_group 0;" ::: "memory")
#define LDSM_X4(r0, r1, r2, r3, addr) \
    asm volatile("ldmatrix.sync.aligned.m8n8.x4.shared.b16 {%0,%1,%2,%3}, [%4];" \
        : "=r"(r0), "=r"(r1), "=r"(r2), "=r"(r3) : "r"(addr))

__device__ __forceinline__ float fast_tanhf(float x) {
    float ax = fabsf(x);
    float e  = __expf(-2.0f * ax);
    float r  = __fdividef(1.0f - e, 1.0f + e);
    return copysignf(r, x);
}
__device__ __forceinline__ float fast_sigmoidf(float x) {
    return 0.5f * fast_tanhf(0.5f * x) + 0.5f;
}
__device__ __forceinline__ float comp(const float4& v, int j) {
    return j == 0 ? v.x : j == 1 ? v.y : j == 2 ? v.z : v.w;
}
__device__ __forceinline__ void fma4(float4& acc, float a, const float4& w) {
    acc.x += a * w.x; acc.y += a * w.y; acc.z += a * w.z; acc.w += a * w.w;
}
__device__ __forceinline__ uint32_t pack2(__nv_bfloat16 a, __nv_bfloat16 b) {
    return (uint32_t)__bfloat16_as_ushort(a) |
           ((uint32_t)__bfloat16_as_ushort(b) << 16);
}
__device__ __forceinline__ void split_f4(float4 v, uint2& h, uint2& l) {
    float f[4] = {v.x, v.y, v.z, v.w};
    unsigned short hb[4], lb[4];
    #pragma unroll
    for (int e = 0; e < 4; e++) {
        __nv_bfloat16 hh = __float2bfloat16(f[e]);
        hb[e] = __bfloat16_as_ushort(hh);
        lb[e] = __bfloat16_as_ushort(__float2bfloat16(f[e] - __bfloat162float(hh)));
    }
    h.x = (uint32_t)hb[0] | ((uint32_t)hb[1] << 16);
    h.y = (uint32_t)hb[2] | ((uint32_t)hb[3] << 16);
    l.x = (uint32_t)lb[0] | ((uint32_t)lb[1] << 16);
    l.y = (uint32_t)lb[2] | ((uint32_t)lb[3] << 16);
}
// m16n8k16 row.col bf16 -> f32 accumulate (base PTX, allowed on compute_100)
__device__ __forceinline__ void mma16816(float* c, const uint32_t* a,
                                         uint32_t b0, uint32_t b1) {
    asm volatile(
        "mma.sync.aligned.m16n8k16.row.col.f32.bf16.bf16.f32 "
        "{%0,%1,%2,%3}, {%4,%5,%6,%7}, {%8,%9}, {%0,%1,%2,%3};"
        : "+f"(c[0]), "+f"(c[1]), "+f"(c[2]), "+f"(c[3])
        : "r"(a[0]), "r"(a[1]), "r"(a[2]), "r"(a[3]), "r"(b0), "r"(b1));
}

// ---------------- weight pre-split: fp32 [k][n] -> bf16 hi/lo [n][64k] -----
__global__ void k_prep(const float* __restrict__ fW, const float* __restrict__ gW,
                       const float* __restrict__ sW, const float* __restrict__ rW)
{
    const int bt = blockIdx.x;            // layer*12 + tile
    const int layer = bt / 12, tl = bt % 12;
    const float* src; int K0;
    if (tl < 4)       { src = fW + (size_t)layer * 2 * RC * RC; K0 = tl * 64; }
    else if (tl < 8)  { src = gW + (size_t)layer * 2 * RC * RC; K0 = (tl - 4) * 64; }
    else if (tl < 10) { src = sW + (size_t)layer * RC * RC;     K0 = (tl - 8) * 64; }
    else              { src = rW + (size_t)layer * RC * RC;     K0 = (tl - 10) * 64; }
    uint32_t* hi_p = (uint32_t*)(g_wprep + (size_t)bt * 2 * 8192);
    uint32_t* lo_p = hi_p + 4096;
    #pragma unroll
    for (int i = 0; i < 16; i++) {
        int u2 = threadIdx.x + i * 256;           // 0..4095 (pairs)
        int n = u2 >> 5, k2 = u2 & 31;
        float w0 = src[(size_t)(K0 + k2 * 2)     * RC + n];
        float w1 = src[(size_t)(K0 + k2 * 2 + 1) * RC + n];
        __nv_bfloat16 h0 = __float2bfloat16(w0), h1 = __float2bfloat16(w1);
        __nv_bfloat16 l0 = __float2bfloat16(w0 - __bfloat162float(h0));
        __nv_bfloat16 l1 = __float2bfloat16(w1 - __bfloat162float(h1));
        hi_p[u2] = pack2(h0, h1);
        lo_p[u2] = pack2(l0, l1);
    }
}

// ---------------- init causal conv (FFMA, unchanged) ----------------
__global__ __launch_bounds__(256, 2)
void k_init(const float* __restrict__ X, const float* __restrict__ W,
            const float* __restrict__ b, float* __restrict__ res)
{
    extern __shared__ float sm[];
    float4* As4 = (float4*)sm;
    float4* Ws4 = (float4*)(sm + 96 * 64);
    const int tid = threadIdx.x;
    const int tx = tid & 31, ty = tid >> 5;
    const int n0 = tx * 4, m0 = ty * 8;
    const int t0 = blockIdx.x * 64;
    const int bstart = t0 & ~(T_LEN - 1);

    const float4* X4 = (const float4*)X;
    #pragma unroll
    for (int i = 0; i < 6; i++) {
        int idx = tid + i * 256;
        if (idx < 95 * 16) {
            int j = idx >> 4, c4 = idx & 15;
            int g = t0 - 31 + j;
            float4 v = make_float4(0.f, 0.f, 0.f, 0.f);
            if (g >= bstart) v = X4[(size_t)g * 16 + c4];
            As4[j * 16 + c4] = v;
        }
    }
    float4 acc[8];
    float4 bias = *(const float4*)&b[n0];
    #pragma unroll
    for (int r = 0; r < 8; r++) acc[r] = bias;
    const float4* W4 = (const float4*)W;
    for (int tap = 0; tap < 32; tap++) {
        __syncthreads();
        #pragma unroll
        for (int i = 0; i < 8; i++) {
            int idx = tid + i * 256;
            int kl = idx >> 5, n4 = idx & 31;
            Ws4[kl * 32 + n4] = W4[(size_t)((tap << 6) + kl) * 32 + n4];
        }
        __syncthreads();
        #pragma unroll
        for (int kk4 = 0; kk4 < 16; kk4++) {
            float4 a[8];
            #pragma unroll
            for (int r = 0; r < 8; r++) a[r] = As4[(m0 + r + tap) * 16 + kk4];
            #pragma unroll
            for (int j = 0; j < 4; j++) {
                float4 w = Ws4[(kk4 * 4 + j) * 32 + tx];
                #pragma unroll
                for (int r = 0; r < 8; r++) fma4(acc[r], comp(a[r], j), w);
            }
        }
    }
    #pragma unroll
    for (int r = 0; r < 8; r++)
        *(float4*)&res[(size_t)(t0 + m0 + r) * RC + n0] = acc[r];
}

// ---------------- tensor-core gated layer: fully pipelined 16k chunks ------
__global__ __launch_bounds__(256, 2)
void k_layer_mma(const float* __restrict__ rin, float* __restrict__ rout,
                 const __nv_bfloat16* __restrict__ wp,
                 const float* __restrict__ fB, const float* __restrict__ gB,
                 const float* __restrict__ sB, const float* __restrict__ rB,
                 float* __restrict__ oacc, int d, int first)
{
    extern __shared__ char smem[];
    const uint32_t sb = smem_u32(smem);
    const int tid = threadIdx.x, wid = tid >> 5, lane = tid & 31;
    const int gr = lane >> 2, cl = lane & 3;
    const int m0 = (wid >> 2) * 32, n0 = (wid & 3) * 32;
    const int t0 = blockIdx.x * 64;
    const int trel = t0 & (T_LEN - 1);
    const char* wpb = (const char*)wp;

    if (tid < 128) {
        ((float*)(smem + SM_BF))[tid] = fB[tid];
        ((float*)(smem + SM_BG))[tid] = gB[tid];
        ((float*)(smem + SM_BS))[tid] = sB[tid];
        ((float*)(smem + SM_BR))[tid] = rB[tid];
    }

    // ldmatrix lane geometry (constant per thread)
    const int rowA = (lane & 7) + ((lane >> 3) & 1) * 8;   // block row for A x4
    const int kA   = ((lane >> 4) & 1) * 16;               // k-half byte offset (A)
    const int rowB = (lane & 7) + ((lane >> 4) & 1) * 8;   // block row for B x4
    const int kB   = ((lane >> 3) & 1) * 16;               // k-half byte offset (B)

    // A-chunk geometry: 64 rows x 16 k = 256 float4, exactly 1 per thread
    const int aM = tid >> 2, aQ = tid & 3;

    // load this thread's float4 of A chunk c (LDG issue only)
    auto load_a = [&](int c, float4& v) {
        int kg = c * 16 + aQ * 4;
        int tm = t0 + aM;
        v = make_float4(0.f, 0.f, 0.f, 0.f);
        if (kg < 128) {
            if (trel + aM >= d)
                v = ((const float4*)rin)[(size_t)(tm - d) * 32 + (kg >> 2)];
        } else {
            v = ((const float4*)rin)[(size_t)tm * 32 + ((kg - 128) >> 2)];
        }
    };
    auto store_a = [&](const float4& v, int buf) {
        uint2 h, l; split_f4(v, h, l);
        int off = SM_A + buf * A_BUF + aM * A_STR + aQ * 8;
        *(uint2*)(smem + off) = h;
        *(uint2*)(smem + off + A_PLANE) = l;
    };
    // stage 4 W planes (matA hi/lo, matB hi/lo) of a 16k sub-chunk via cp.async
    // tile row = 128B (64k), sub-chunk ch in 0..3 -> +ch*32 bytes
    auto stage_w = [&](int tileA, int tileB, int ch, int buf) {
        #pragma unroll
        for (int i = 0; i < 4; i++) {
            int idx = tid + i * 256;              // 0..1023 16B units
            int pl = idx >> 8, rem = idx & 255;
            int n = rem >> 1, q = rem & 1;
            int tile = (pl >> 1) ? tileB : tileA;
            int plane = pl & 1;
            const char* src = wpb + (size_t)tile * 32768 + plane * 16384
                            + n * 128 + ch * 32 + q * 16;
            uint32_t dst = sb + SM_W + buf * W_BUF + pl * W_PLANE + n * A_STR + q * 16;
            CP_ASYNC16(dst, src);
        }
    };

    float accA[2][4][4], accB[2][4][4];
    #pragma unroll
    for (int mr = 0; mr < 2; mr++)
        #pragma unroll
        for (int nc = 0; nc < 4; nc++)
            #pragma unroll
            for (int e = 0; e < 4; e++) { accA[mr][nc][e] = 0.f; accB[mr][nc][e] = 0.f; }

    // MMA over one 16k chunk: 4 A-LDSM + 8 B-LDSM + 48 HMMA (pass-reordered)
    auto mma_chunk = [&](int a_base, int a_stride, int lo_delta, int wbuf) {
        uint32_t ah[2][4], al[2][4];
        #pragma unroll
        for (int mr = 0; mr < 2; mr++) {
            uint32_t aaddr = sb + a_base + (m0 + mr * 16 + rowA) * a_stride + kA;
            LDSM_X4(ah[mr][0], ah[mr][1], ah[mr][2], ah[mr][3], aaddr);
            LDSM_X4(al[mr][0], al[mr][1], al[mr][2], al[mr][3], aaddr + lo_delta);
        }
        uint32_t bf[2][2][4][2];                  // [mat][plane][nc][reg]
        #pragma unroll
        for (int mat = 0; mat < 2; mat++)
            #pragma unroll
            for (int pl = 0; pl < 2; pl++)
                #pragma unroll
                for (int p = 0; p < 2; p++) {
                    uint32_t baddr = sb + SM_W + wbuf * W_BUF
                                   + (mat * 2 + pl) * W_PLANE
                                   + (n0 + p * 16 + rowB) * A_STR + kB;
                    LDSM_X4(bf[mat][pl][2*p][0], bf[mat][pl][2*p][1],
                            bf[mat][pl][2*p+1][0], bf[mat][pl][2*p+1][1], baddr);
                }
        #pragma unroll
        for (int mat = 0; mat < 2; mat++)
            #pragma unroll
            for (int nc = 0; nc < 4; nc++)
                #pragma unroll
                for (int mr = 0; mr < 2; mr++) {
                    float* cc = mat ? accB[mr][nc] : accA[mr][nc];
                    mma16816(cc, ah[mr], bf[mat][0][nc][0], bf[mat][0][nc][1]);
                }
        #pragma unroll
        for (int mat = 0; mat < 2; mat++)
            #pragma unroll
            for (int nc = 0; nc < 4; nc++)
                #pragma unroll
                for (int mr = 0; mr < 2; mr++) {
                    float* cc = mat ? accB[mr][nc] : accA[mr][nc];
                    mma16816(cc, ah[mr], bf[mat][1][nc][0], bf[mat][1][nc][1]);
                }
        #pragma unroll
        for (int mat = 0; mat < 2; mat++)
            #pragma unroll
            for (int nc = 0; nc < 4; nc++)
                #pragma unroll
                for (int mr = 0; mr < 2; mr++) {
                    float* cc = mat ? accB[mr][nc] : accA[mr][nc];
                    mma16816(cc, al[mr], bf[mat][0][nc][0], bf[mat][0][nc][1]);
                }
    };

    // ======== phase 1: F = A@Wf, G = A@Wg over K=256 (16 chunks of 16) =====
    {
        float4 av0;
        load_a(0, av0);
        stage_w(0, 4, 0, 0); CP_COMMIT();
        store_a(av0, 0);
        CP_WAIT0();
        __syncthreads();
    }
    for (int c = 0; c < 16; c++) {
        int cur = c & 1, nxt = cur ^ 1;
        float4 av;
        if (c < 15) {
            load_a(c + 1, av);                    // LDG under this chunk's MMA
            stage_w((c + 1) >> 2, 4 + ((c + 1) >> 2), (c + 1) & 3, nxt);
            CP_COMMIT();                          // cp.async under MMA
        }
        mma_chunk(SM_A + cur * A_BUF, A_STR, A_PLANE, cur);
        if (c < 15) {
            store_a(av, nxt);                     // cheap split+STS after MMA
            CP_WAIT0();
        }
        __syncthreads();
    }

    // prefetch phase-2 chunk 0 W under the activation epilogue
    stage_w(8, 10, 0, 0); CP_COMMIT();

    // ======== epilogue 1: gated activation, split P into smem ========
    {
        const float* bFp = (const float*)(smem + SM_BF);
        const float* bGp = (const float*)(smem + SM_BG);
        #pragma unroll
        for (int mr = 0; mr < 2; mr++)
            #pragma unroll
            for (int nc = 0; nc < 4; nc++) {
                int m = m0 + mr * 16 + gr, n = n0 + nc * 8 + cl * 2;
                #pragma unroll
                for (int h = 0; h < 2; h++) {
                    float f0 = accA[mr][nc][h * 2 + 0] + bFp[n];
                    float f1 = accA[mr][nc][h * 2 + 1] + bFp[n + 1];
                    float g0 = accB[mr][nc][h * 2 + 0] + bGp[n];
                    float g1 = accB[mr][nc][h * 2 + 1] + bGp[n + 1];
                    float p0 = fast_tanhf(f0) * fast_sigmoidf(g0);
                    float p1 = fast_tanhf(f1) * fast_sigmoidf(g1);
                    __nv_bfloat16 h0 = __float2bfloat16(p0);
                    __nv_bfloat16 h1 = __float2bfloat16(p1);
                    __nv_bfloat16 l0 = __float2bfloat16(p0 - __bfloat162float(h0));
                    __nv_bfloat16 l1 = __float2bfloat16(p1 - __bfloat162float(h1));
                    int off = SM_P + (m + h * 8) * P_STR + n * 2;
                    *(uint32_t*)(smem + off) = pack2(h0, h1);
                    *(uint32_t*)(smem + off + P_PLANE) = pack2(l0, l1);
                }
            }
    }
    #pragma unroll
    for (int mr = 0; mr < 2; mr++)
        #pragma unroll
        for (int nc = 0; nc < 4; nc++)
            #pragma unroll
            for (int e = 0; e < 4; e++) { accA[mr][nc][e] = 0.f; accB[mr][nc][e] = 0.f; }
    CP_WAIT0();
    __syncthreads();

    // ======== phase 2: S = P@Ws, R = P@Wr over K=128 (8 chunks of 16) ======
    for (int c2 = 0; c2 < 8; c2++) {
        int cur = c2 & 1, nxt = cur ^ 1;
        if (c2 < 7) {
            stage_w(8 + ((c2 + 1) >> 2), 10 + ((c2 + 1) >> 2), (c2 + 1) & 3, nxt);
            CP_COMMIT();
        }
        mma_chunk(SM_P + c2 * 32, P_STR, P_PLANE, cur);
        if (c2 < 7) CP_WAIT0();
        __syncthreads();
    }

    // ======== epilogue 2: residual + skip accumulator update ========
    {
        const float* bSp = (const float*)(smem + SM_BS);
        const float* bRp = (const float*)(smem + SM_BR);
        #pragma unroll
        for (int mr = 0; mr < 2; mr++)
            #pragma unroll
            for (int nc = 0; nc < 4; nc++) {
                int m = m0 + mr * 16 + gr, n = n0 + nc * 8 + cl * 2;
                #pragma unroll
                for (int h = 0; h < 2; h++) {
                    size_t gi = (size_t)(t0 + m + h * 8) * RC + n;
                    float2 rold = *(const float2*)&rin[gi];
                    float2 rnew;
                    rnew.x = rold.x + accB[mr][nc][h * 2 + 0] + bRp[n];
                    rnew.y = rold.y + accB[mr][nc][h * 2 + 1] + bRp[n + 1];
                    *(float2*)&rout[gi] = rnew;
                    float2 s;
                    s.x = accA[mr][nc][h * 2 + 0] + bSp[n];
                    s.y = accA[mr][nc][h * 2 + 1] + bSp[n + 1];
                    if (!first) {
                        float2 o = *(const float2*)&oacc[gi];
                        s.x += o.x; s.y += o.y;
                    }
                    *(float2*)&oacc[gi] = s;
                }
            }
    }
}

// ---------------- fused skip stack (unchanged) ----------------
#define SK_W0   0
#define SK_WR   4096
#define SK_WF   35840
#define SK_B0   44032
#define SK_BR   44064
#define SK_BF   45056
#define SK_TOT  45312

__global__ __launch_bounds__(512)
void k_skip(const float* __restrict__ oacc,
            const float* __restrict__ w0, const float* __restrict__ b0,
            const float* __restrict__ wr, const float* __restrict__ br,
            const float* __restrict__ wf, const float* __restrict__ bf,
            float* __restrict__ y)
{
    extern __shared__ float sm[];
    const int tid = threadIdx.x;
    for (int i = tid; i < 4096;  i += 512) sm[SK_W0 + i] = w0[i];
    for (int i = tid; i < 31744; i += 512) sm[SK_WR + i] = wr[i];
    for (int i = tid; i < 8192;  i += 512) sm[SK_WF + i] = wf[i];
    for (int i = tid; i < 32;    i += 512) sm[SK_B0 + i] = b0[i];
    for (int i = tid; i < 992;   i += 512) sm[SK_BR + i] = br[i];
    for (int i = tid; i < 256;   i += 512) sm[SK_BF + i] = bf[i];
    __syncthreads();

    const int row = blockIdx.x * 512 + tid;
    float h[32];
    #pragma unroll
    for (int c = 0; c < 32; c++) h[c] = sm[SK_B0 + c];

    const float4* in4 = (const float4*)(oacc + (size_t)row * RC);
    const float4* w0_4 = (const float4*)(sm + SK_W0);
    #pragma unroll 4
    for (int k4 = 0; k4 < 32; k4++) {
        float4 x = __ldg(&in4[k4]);
        x.x = fmaxf(x.x, 0.f); x.y = fmaxf(x.y, 0.f);
        x.z = fmaxf(x.z, 0.f); x.w = fmaxf(x.w, 0.f);
        #pragma unroll
        for (int j = 0; j < 4; j++) {
            float xv = comp(x, j);
            #pragma unroll
            for (int c4 = 0; c4 < 8; c4++) {
                float4 w = w0_4[(k4 * 4 + j) * 8 + c4];
                h[c4*4+0] += xv * w.x; h[c4*4+1] += xv * w.y;
                h[c4*4+2] += xv * w.z; h[c4*4+3] += xv * w.w;
            }
        }
    }
    #pragma unroll 1
    for (int step = 0; step < 31; step++) {
        float hn[32];
        #pragma unroll
        for (int c = 0; c < 32; c++) hn[c] = sm[SK_BR + step * 32 + c];
        const float4* wr4 = (const float4*)(sm + SK_WR + step * 1024);
        #pragma unroll
        for (int k = 0; k < 32; k++) {
            float xv = fmaxf(h[k], 0.f);
            #pragma unroll
            for (int c4 = 0; c4 < 8; c4++) {
                float4 w = wr4[k * 8 + c4];
                hn[c4*4+0] += xv * w.x; hn[c4*4+1] += xv * w.y;
                hn[c4*4+2] += xv * w.z; hn[c4*4+3] += xv * w.w;
            }
        }
        #pragma unroll
        for (int c = 0; c < 32; c++) h[c] = hn[c];
    }
    float rh[32];
    #pragma unroll
    for (int k = 0; k < 32; k++) rh[k] = fmaxf(h[k], 0.f);
    const float4* wf4 = (const float4*)(sm + SK_WF);
    const float4* bf4 = (const float4*)(sm + SK_BF);
    float* yrow = y + (size_t)row * 256;
    #pragma unroll 1
    for (int g = 0; g < 8; g++) {
        float4 acc[8];
        #pragma unroll
        for (int c4 = 0; c4 < 8; c4++) acc[c4] = bf4[g * 8 + c4];
        #pragma unroll
        for (int k = 0; k < 32; k++) {
            float xv = rh[k];
            #pragma unroll
            for (int c4 = 0; c4 < 8; c4++) {
                float4 w = wf4[k * 64 + g * 8 + c4];
                acc[c4].x += xv * w.x; acc[c4].y += xv * w.y;
                acc[c4].z += xv * w.z; acc[c4].w += xv * w.w;
            }
        }
        #pragma unroll
        for (int c4 = 0; c4 < 8; c4++)
            *(float4*)&yrow[g * 32 + c4 * 4] = acc[c4];
    }
}

// ---------------- launch ----------------
extern "C" void kernel_launch(void* const* d_in, const int* in_sizes, int n_in,
                              void* d_out, int out_size)
{
    const float* X      = (const float*)d_in[0];
    const float* init_w = (const float*)d_in[1];
    const float* init_b = (const float*)d_in[2];
    const float* f_w    = (const float*)d_in[3];
    const float* f_b    = (const float*)d_in[4];
    const float* g_w    = (const float*)d_in[5];
    const float* g_b    = (const float*)d_in[6];
    const float* skip_w = (const float*)d_in[7];
    const float* skip_b = (const float*)d_in[8];
    const float* res_w  = (const float*)d_in[9];
    const float* res_b  = (const float*)d_in[10];
    const float* sk0_w  = (const float*)d_in[11];
    const float* sk0_b  = (const float*)d_in[12];
    const float* skr_w  = (const float*)d_in[13];
    const float* skr_b  = (const float*)d_in[14];
    const float* fin_w  = (const float*)d_in[15];
    const float* fin_b  = (const float*)d_in[16];

    float *r0, *r1, *oa;
    __nv_bfloat16* wpre;
    cudaGetSymbolAddress((void**)&r0, g_res0);
    cudaGetSymbolAddress((void**)&r1, g_res1);
    cudaGetSymbolAddress((void**)&oa, g_skipacc);
    cudaGetSymbolAddress((void**)&wpre, g_wprep);

    const int SM_INIT  = 96 * 64 * 4 + 64 * 128 * 4;   // 57344
    const int SM_SKIP  = SK_TOT * 4;                   // 181248
    cudaFuncSetAttribute(k_init,      cudaFuncAttributeMaxDynamicSharedMemorySize, SM_INIT);
    cudaFuncSetAttribute(k_layer_mma, cudaFuncAttributeMaxDynamicSharedMemorySize, SM_TOTAL);
    cudaFuncSetAttribute(k_skip,      cudaFuncAttributeMaxDynamicSharedMemorySize, SM_SKIP);

    k_prep<<<NLAYERS * 12, 256>>>(f_w, g_w, skip_w, res_w);
    k_init<<<M_ROWS / 64, 256, SM_INIT>>>(X, init_w, init_b, r0);

    const float* rin = r0;
    float* rout = r1;
    for (int i = 0; i < NLAYERS; i++) {
        k_layer_mma<<<M_ROWS / 64, 256, SM_TOTAL>>>(
            rin, rout,
            wpre + (size_t)i * 12 * 2 * 8192,
            f_b + (size_t)i * RC, g_b + (size_t)i * RC,
            skip_b + (size_t)i * RC, res_b + (size_t)i * RC,
            oa, H_DIL[i], (i == 0) ? 1 : 0);
        const float* t = rin; rin = rout; rout = (float*)t;
    }

    k_skip<<<M_ROWS / 512, 512, SM_SKIP>>>(oa, sk0_w, sk0_b, skr_w, skr_b,
                                           fin_w, fin_b, (float*)d_out);
}

// round 13
// speedup vs baseline: 1.2007x; 1.2007x over previous
#include <cuda_runtime.h>
#include <cuda_bf16.h>
#include <cstdint>

#define M_ROWS 65536
#define T_LEN  16384
#define RC     128
#define NLAYERS 20

// ---- smem layout for k_layer_mma (bytes) ---- (R10 layout, best known)
#define SM_BF     0
#define SM_BG     512
#define SM_BS     1024
#define SM_BR     1536
#define SM_A      2048
#define A_STR     80
#define A_PLANE   5120
#define SM_W      12288
#define W_PLANE   10240
#define SM_P      53248
#define P_STR     272
#define P_PLANE   17408
#define SM_TOTAL  88064

// ---- smem layout for k_init_mma (bytes) ----
#define SI_B      0           // bias 512
#define SI_XS     1024        // 96 rows * 144B, hi+lo
#define X_STR     144
#define X_PLANE   13824
#define SI_W      28672       // 2 bufs * 2 planes * (128*144)
#define WI_PLANE  18432
#define WI_BUF    36864
#define SI_TOTAL  102400

// ---------------- device scratch ----------------
__device__ float g_res0[(size_t)M_ROWS * RC];
__device__ float g_res1[(size_t)M_ROWS * RC];
__device__ float g_skipacc[(size_t)M_ROWS * RC];
// layer weights: [layer][12 tiles][2 planes][8192 bf16], tile=[128n][64k] k-contig
__device__ __nv_bfloat16 g_wprep[(size_t)NLAYERS * 12 * 2 * 8192];
// init weights: [tap(32)][2 planes][128n x 64k bf16]
__device__ __nv_bfloat16 g_wprep_init[(size_t)32 * 2 * 8192];

static const int H_DIL[NLAYERS] = {1,2,4,8,16,32,64,128,256,512,
                                   1,2,4,8,16,32,64,128,256,512};

// ---------------- helpers ----------------
__device__ __forceinline__ uint32_t smem_u32(const void* p) {
    uint32_t a;
    asm("{ .reg .u64 t; cvta.to.shared.u64 t, %1; cvt.u32.u64 %0, t; }"
        : "=r"(a) : "l"(p));
    return a;
}
#define CP_ASYNC16(dst_u32, src_ptr) \
    asm volatile("cp.async.cg.shared.global [%0], [%1], 16;" \
        :: "r"(dst_u32), "l"(src_ptr) : "memory")
#define CP_COMMIT() asm volatile("cp.async.commit_group;" ::: "memory")
#define CP_WAIT0()  asm volatile("cp.async.wait_group 0;" ::: "memory")
#define LDSM_X4(r0, r1, r2, r3, addr) \
    asm volatile("ldmatrix.sync.aligned.m8n8.x4.shared.b16 {%0,%1,%2,%3}, [%4];" \
        : "=r"(r0), "=r"(r1), "=r"(r2), "=r"(r3) : "r"(addr))

__device__ __forceinline__ float fast_tanhf(float x) {
    float ax = fabsf(x);
    float e  = __expf(-2.0f * ax);
    float r  = __fdividef(1.0f - e, 1.0f + e);
    return copysignf(r, x);
}
__device__ __forceinline__ float fast_sigmoidf(float x) {
    return 0.5f * fast_tanhf(0.5f * x) + 0.5f;
}
__device__ __forceinline__ float comp(const float4& v, int j) {
    return j == 0 ? v.x : j == 1 ? v.y : j == 2 ? v.z : v.w;
}
__device__ __forceinline__ void fma4(float4& acc, float a, const float4& w) {
    acc.x += a * w.x; acc.y += a * w.y; acc.z += a * w.z; acc.w += a * w.w;
}
__device__ __forceinline__ uint32_t pack2(__nv_bfloat16 a, __nv_bfloat16 b) {
    return (uint32_t)__bfloat16_as_ushort(a) |
           ((uint32_t)__bfloat16_as_ushort(b) << 16);
}
__device__ __forceinline__ void split_f4(float4 v, uint2& h, uint2& l) {
    float f[4] = {v.x, v.y, v.z, v.w};
    unsigned short hb[4], lb[4];
    #pragma unroll
    for (int e = 0; e < 4; e++) {
        __nv_bfloat16 hh = __float2bfloat16(f[e]);
        hb[e] = __bfloat16_as_ushort(hh);
        lb[e] = __bfloat16_as_ushort(__float2bfloat16(f[e] - __bfloat162float(hh)));
    }
    h.x = (uint32_t)hb[0] | ((uint32_t)hb[1] << 16);
    h.y = (uint32_t)hb[2] | ((uint32_t)hb[3] << 16);
    l.x = (uint32_t)lb[0] | ((uint32_t)lb[1] << 16);
    l.y = (uint32_t)lb[2] | ((uint32_t)lb[3] << 16);
}
__device__ __forceinline__ void mma16816(float* c, const uint32_t* a,
                                         uint32_t b0, uint32_t b1) {
    asm volatile(
        "mma.sync.aligned.m16n8k16.row.col.f32.bf16.bf16.f32 "
        "{%0,%1,%2,%3}, {%4,%5,%6,%7}, {%8,%9}, {%0,%1,%2,%3};"
        : "+f"(c[0]), "+f"(c[1]), "+f"(c[2]), "+f"(c[3])
        : "r"(a[0]), "r"(a[1]), "r"(a[2]), "r"(a[3]), "r"(b0), "r"(b1));
}

// ---------------- layer weight pre-split ----------------
__global__ void k_prep(const float* __restrict__ fW, const float* __restrict__ gW,
                       const float* __restrict__ sW, const float* __restrict__ rW)
{
    const int bt = blockIdx.x;
    const int layer = bt / 12, tl = bt % 12;
    const float* src; int K0;
    if (tl < 4)       { src = fW + (size_t)layer * 2 * RC * RC; K0 = tl * 64; }
    else if (tl < 8)  { src = gW + (size_t)layer * 2 * RC * RC; K0 = (tl - 4) * 64; }
    else if (tl < 10) { src = sW + (size_t)layer * RC * RC;     K0 = (tl - 8) * 64; }
    else              { src = rW + (size_t)layer * RC * RC;     K0 = (tl - 10) * 64; }
    uint32_t* hi_p = (uint32_t*)(g_wprep + (size_t)bt * 2 * 8192);
    uint32_t* lo_p = hi_p + 4096;
    #pragma unroll
    for (int i = 0; i < 16; i++) {
        int u2 = threadIdx.x + i * 256;
        int n = u2 >> 5, k2 = u2 & 31;
        float w0 = src[(size_t)(K0 + k2 * 2)     * RC + n];
        float w1 = src[(size_t)(K0 + k2 * 2 + 1) * RC + n];
        __nv_bfloat16 h0 = __float2bfloat16(w0), h1 = __float2bfloat16(w1);
        __nv_bfloat16 l0 = __float2bfloat16(w0 - __bfloat162float(h0));
        __nv_bfloat16 l1 = __float2bfloat16(w1 - __bfloat162float(h1));
        hi_p[u2] = pack2(h0, h1);
        lo_p[u2] = pack2(l0, l1);
    }
}

// ---------------- init weight pre-split: W[tap][k][n] -> [tap][n][64k] -----
__global__ void k_prep_init(const float* __restrict__ iW)
{
    const int tap = blockIdx.x;                   // 0..31
    const float* src = iW + (size_t)tap * 64 * RC;
    uint32_t* hi_p = (uint32_t*)(g_wprep_init + (size_t)tap * 2 * 8192);
    uint32_t* lo_p = hi_p + 4096;
    #pragma unroll
    for (int i = 0; i < 16; i++) {
        int u2 = threadIdx.x + i * 256;           // 0..4095 (k pairs)
        int n = u2 >> 5, k2 = u2 & 31;
        float w0 = src[(size_t)(k2 * 2)     * RC + n];
        float w1 = src[(size_t)(k2 * 2 + 1) * RC + n];
        __nv_bfloat16 h0 = __float2bfloat16(w0), h1 = __float2bfloat16(w1);
        __nv_bfloat16 l0 = __float2bfloat16(w0 - __bfloat162float(h0));
        __nv_bfloat16 l1 = __float2bfloat16(w1 - __bfloat162float(h1));
        hi_p[u2] = pack2(h0, h1);
        lo_p[u2] = pack2(l0, l1);
    }
}

// ---------------- init causal conv on tensor cores ----------------
// out[t] = sum_tap X[t-31+tap] @ W[tap]; A (X halo) resident in smem,
// W double-buffered per tap via cp.async.
// FIX vs R12: each tap covers K=64 -> FOUR 16-k ldmatrix/MMA steps (ks*32B),
// not two 64B-offset steps.
__global__ __launch_bounds__(256, 2)
void k_init_mma(const float* __restrict__ X, const float* __restrict__ b,
                float* __restrict__ res)
{
    extern __shared__ char smem[];
    const uint32_t sb = smem_u32(smem);
    const int tid = threadIdx.x, wid = tid >> 5, lane = tid & 31;
    const int gr = lane >> 2, cl = lane & 3;
    const int m0 = (wid >> 2) * 32, n0 = (wid & 3) * 32;
    const int t0 = blockIdx.x * 64;
    const int bstart = t0 & ~(T_LEN - 1);
    const char* wpb = (const char*)g_wprep_init;

    const int rowA = (lane & 7) + ((lane >> 3) & 1) * 8;
    const int kA   = ((lane >> 4) & 1) * 16;
    const int rowB = (lane & 7) + ((lane >> 4) & 1) * 8;
    const int kB   = ((lane >> 3) & 1) * 16;

    if (tid < 128) ((float*)(smem + SI_B))[tid] = b[tid];

    // stage W for tap `tp` into buffer `buf` (2 planes x 18KB padded)
    auto stage_wi = [&](int tp, int buf) {
        #pragma unroll
        for (int i = 0; i < 8; i++) {
            int idx = tid + i * 256;              // 0..2047 16B units
            int pl = idx >> 10, rem = idx & 1023;
            int n = rem >> 3, q = rem & 7;
            const char* src = wpb + (size_t)tp * 32768 + pl * 16384
                            + n * 128 + q * 16;
            uint32_t dst = sb + SI_W + buf * WI_BUF + pl * WI_PLANE
                         + n * X_STR + q * 16;
            CP_ASYNC16(dst, src);
        }
    };

    // kick off tap-0 W load, then stage resident X halo (95 rows x 64 ch)
    stage_wi(0, 0); CP_COMMIT();
    {
        const float4* X4 = (const float4*)X;
        #pragma unroll
        for (int i = 0; i < 6; i++) {
            int idx = tid + i * 256;
            if (idx < 95 * 16) {
                int j = idx >> 4, c4 = idx & 15;
                int g = t0 - 31 + j;
                float4 v = make_float4(0.f, 0.f, 0.f, 0.f);
                if (g >= bstart) v = X4[(size_t)g * 16 + c4];
                uint2 h, l; split_f4(v, h, l);
                int off = SI_XS + j * X_STR + c4 * 8;
                *(uint2*)(smem + off) = h;
                *(uint2*)(smem + off + X_PLANE) = l;
            }
        }
    }
    CP_WAIT0();
    __syncthreads();

    float acc[2][4][4];
    #pragma unroll
    for (int mr = 0; mr < 2; mr++)
        #pragma unroll
        for (int nc = 0; nc < 4; nc++)
            #pragma unroll
            for (int e = 0; e < 4; e++) acc[mr][nc][e] = 0.f;

    for (int tap = 0; tap < 32; tap++) {
        int cur = tap & 1, nxt = cur ^ 1;
        if (tap < 31) { stage_wi(tap + 1, nxt); CP_COMMIT(); }
        #pragma unroll
        for (int ks = 0; ks < 4; ks++) {          // 4 x 16-k steps = K=64
            uint32_t ah[2][4], al[2][4];
            #pragma unroll
            for (int mr = 0; mr < 2; mr++) {
                uint32_t aaddr = sb + SI_XS
                               + (m0 + mr * 16 + rowA + tap) * X_STR
                               + ks * 32 + kA;
                LDSM_X4(ah[mr][0], ah[mr][1], ah[mr][2], ah[mr][3], aaddr);
                LDSM_X4(al[mr][0], al[mr][1], al[mr][2], al[mr][3], aaddr + X_PLANE);
            }
            uint32_t bf[2][4][2];                 // [plane][nc][reg]
            #pragma unroll
            for (int pl = 0; pl < 2; pl++)
                #pragma unroll
                for (int p = 0; p < 2; p++) {
                    uint32_t baddr = sb + SI_W + cur * WI_BUF + pl * WI_PLANE
                                   + (n0 + p * 16 + rowB) * X_STR + ks * 32 + kB;
                    LDSM_X4(bf[pl][2*p][0], bf[pl][2*p][1],
                            bf[pl][2*p+1][0], bf[pl][2*p+1][1], baddr);
                }
            #pragma unroll
            for (int nc = 0; nc < 4; nc++)
                #pragma unroll
                for (int mr = 0; mr < 2; mr++)
                    mma16816(acc[mr][nc], ah[mr], bf[0][nc][0], bf[0][nc][1]);
            #pragma unroll
            for (int nc = 0; nc < 4; nc++)
                #pragma unroll
                for (int mr = 0; mr < 2; mr++)
                    mma16816(acc[mr][nc], ah[mr], bf[1][nc][0], bf[1][nc][1]);
            #pragma unroll
            for (int nc = 0; nc < 4; nc++)
                #pragma unroll
                for (int mr = 0; mr < 2; mr++)
                    mma16816(acc[mr][nc], al[mr], bf[0][nc][0], bf[0][nc][1]);
        }
        if (tap < 31) CP_WAIT0();
        __syncthreads();
    }

    // epilogue: add bias, store fp32
    {
        const float* bp = (const float*)(smem + SI_B);
        #pragma unroll
        for (int mr = 0; mr < 2; mr++)
            #pragma unroll
            for (int nc = 0; nc < 4; nc++) {
                int m = m0 + mr * 16 + gr, n = n0 + nc * 8 + cl * 2;
                #pragma unroll
                for (int h = 0; h < 2; h++) {
                    size_t gi = (size_t)(t0 + m + h * 8) * RC + n;
                    float2 o;
                    o.x = acc[mr][nc][h * 2 + 0] + bp[n];
                    o.y = acc[mr][nc][h * 2 + 1] + bp[n + 1];
                    *(float2*)&res[gi] = o;
                }
            }
    }
}

// ---------------- tensor-core gated layer (R10 version, best known) --------
__global__ __launch_bounds__(256, 2)
void k_layer_mma(const float* __restrict__ rin, float* __restrict__ rout,
                 const __nv_bfloat16* __restrict__ wp,
                 const float* __restrict__ fB, const float* __restrict__ gB,
                 const float* __restrict__ sB, const float* __restrict__ rB,
                 float* __restrict__ oacc, int d, int first)
{
    extern __shared__ char smem[];
    const uint32_t sb = smem_u32(smem);
    const int tid = threadIdx.x, wid = tid >> 5, lane = tid & 31;
    const int gr = lane >> 2, cl = lane & 3;
    const int m0 = (wid >> 2) * 32, n0 = (wid & 3) * 32;
    const int t0 = blockIdx.x * 64;
    const int trel = t0 & (T_LEN - 1);
    const char* wpb = (const char*)wp;

    if (tid < 128) {
        ((float*)(smem + SM_BF))[tid] = fB[tid];
        ((float*)(smem + SM_BG))[tid] = gB[tid];
        ((float*)(smem + SM_BS))[tid] = sB[tid];
        ((float*)(smem + SM_BR))[tid] = rB[tid];
    }

    const int rowA = (lane & 7) + ((lane >> 3) & 1) * 8;
    const int kA   = ((lane >> 4) & 1) * 16;
    const int rowB = (lane & 7) + ((lane >> 4) & 1) * 8;
    const int kB   = ((lane >> 3) & 1) * 16;

    auto load_a = [&](int c, float4* v) {
        #pragma unroll
        for (int i = 0; i < 2; i++) {
            int idx = tid + i * 256;
            int m = idx >> 3, q = idx & 7;
            int kg = c * 32 + q * 4;
            int tm = t0 + m;
            v[i] = make_float4(0.f, 0.f, 0.f, 0.f);
            if (kg < 128) {
                if (trel + m >= d)
                    v[i] = ((const float4*)rin)[(size_t)(tm - d) * 32 + (kg >> 2)];
            } else {
                v[i] = ((const float4*)rin)[(size_t)tm * 32 + ((kg - 128) >> 2)];
            }
        }
    };
    auto store_a = [&](const float4* v) {
        #pragma unroll
        for (int i = 0; i < 2; i++) {
            int idx = tid + i * 256;
            int m = idx >> 3, q = idx & 7;
            uint2 h, l; split_f4(v[i], h, l);
            int off = SM_A + m * A_STR + q * 8;
            *(uint2*)(smem + off) = h;
            *(uint2*)(smem + off + A_PLANE) = l;
        }
    };
    auto stage_w = [&](int tileA, int tileB, int ch) {
        #pragma unroll
        for (int i = 0; i < 8; i++) {
            int idx = tid + i * 256;
            int pl = idx >> 9, rem = idx & 511;
            int n = rem >> 2, q = rem & 3;
            int tile = (pl >> 1) ? tileB : tileA;
            int plane = pl & 1;
            const char* src = wpb + (size_t)tile * 32768 + plane * 16384
                            + n * 128 + ch * 64 + q * 16;
            uint32_t dst = sb + SM_W + pl * W_PLANE + n * A_STR + q * 16;
            CP_ASYNC16(dst, src);
        }
    };

    float accA[2][4][4], accB[2][4][4];
    #pragma unroll
    for (int mr = 0; mr < 2; mr++)
        #pragma unroll
        for (int nc = 0; nc < 4; nc++)
            #pragma unroll
            for (int e = 0; e < 4; e++) { accA[mr][nc][e] = 0.f; accB[mr][nc][e] = 0.f; }

    auto mma_chunk = [&](int a_base, int a_stride, int lo_delta) {
        #pragma unroll
        for (int ks = 0; ks < 2; ks++) {
            uint32_t ah[2][4], al[2][4];
            #pragma unroll
            for (int mr = 0; mr < 2; mr++) {
                uint32_t aaddr = sb + a_base + (m0 + mr * 16 + rowA) * a_stride
                               + ks * 32 + kA;
                LDSM_X4(ah[mr][0], ah[mr][1], ah[mr][2], ah[mr][3], aaddr);
                LDSM_X4(al[mr][0], al[mr][1], al[mr][2], al[mr][3], aaddr + lo_delta);
            }
            uint32_t bf[2][2][4][2];
            #pragma unroll
            for (int mat = 0; mat < 2; mat++)
                #pragma unroll
                for (int pl = 0; pl < 2; pl++)
                    #pragma unroll
                    for (int p = 0; p < 2; p++) {
                        uint32_t baddr = sb + SM_W + (mat * 2 + pl) * W_PLANE
                                       + (n0 + p * 16 + rowB) * A_STR + ks * 32 + kB;
                        LDSM_X4(bf[mat][pl][2*p][0], bf[mat][pl][2*p][1],
                                bf[mat][pl][2*p+1][0], bf[mat][pl][2*p+1][1], baddr);
                    }
            #pragma unroll
            for (int mat = 0; mat < 2; mat++)
                #pragma unroll
                for (int nc = 0; nc < 4; nc++)
                    #pragma unroll
                    for (int mr = 0; mr < 2; mr++) {
                        float* cc = mat ? accB[mr][nc] : accA[mr][nc];
                        mma16816(cc, ah[mr], bf[mat][0][nc][0], bf[mat][0][nc][1]);
                    }
            #pragma unroll
            for (int mat = 0; mat < 2; mat++)
                #pragma unroll
                for (int nc = 0; nc < 4; nc++)
                    #pragma unroll
                    for (int mr = 0; mr < 2; mr++) {
                        float* cc = mat ? accB[mr][nc] : accA[mr][nc];
                        mma16816(cc, ah[mr], bf[mat][1][nc][0], bf[mat][1][nc][1]);
                    }
            #pragma unroll
            for (int mat = 0; mat < 2; mat++)
                #pragma unroll
                for (int nc = 0; nc < 4; nc++)
                    #pragma unroll
                    for (int mr = 0; mr < 2; mr++) {
                        float* cc = mat ? accB[mr][nc] : accA[mr][nc];
                        mma16816(cc, al[mr], bf[mat][0][nc][0], bf[mat][0][nc][1]);
                    }
        }
    };

    // phase 1: K=256 in 8 chunks of 32
    for (int c = 0; c < 8; c++) {
        if (c) __syncthreads();
        float4 av[2];
        load_a(c, av);
        stage_w(c >> 1, 4 + (c >> 1), c & 1);
        CP_COMMIT();
        store_a(av);
        CP_WAIT0();
        __syncthreads();
        mma_chunk(SM_A, A_STR, A_PLANE);
    }

    // epilogue 1
    __syncthreads();
    {
        const float* bFp = (const float*)(smem + SM_BF);
        const float* bGp = (const float*)(smem + SM_BG);
        #pragma unroll
        for (int mr = 0; mr < 2; mr++)
            #pragma unroll
            for (int nc = 0; nc < 4; nc++) {
                int m = m0 + mr * 16 + gr, n = n0 + nc * 8 + cl * 2;
                #pragma unroll
                for (int h = 0; h < 2; h++) {
                    float f0 = accA[mr][nc][h * 2 + 0] + bFp[n];
                    float f1 = accA[mr][nc][h * 2 + 1] + bFp[n + 1];
                    float g0 = accB[mr][nc][h * 2 + 0] + bGp[n];
                    float g1 = accB[mr][nc][h * 2 + 1] + bGp[n + 1];
                    float p0 = fast_tanhf(f0) * fast_sigmoidf(g0);
                    float p1 = fast_tanhf(f1) * fast_sigmoidf(g1);
                    __nv_bfloat16 h0 = __float2bfloat16(p0);
                    __nv_bfloat16 h1 = __float2bfloat16(p1);
                    __nv_bfloat16 l0 = __float2bfloat16(p0 - __bfloat162float(h0));
                    __nv_bfloat16 l1 = __float2bfloat16(p1 - __bfloat162float(h1));
                    int off = SM_P + (m + h * 8) * P_STR + n * 2;
                    *(uint32_t*)(smem + off) = pack2(h0, h1);
                    *(uint32_t*)(smem + off + P_PLANE) = pack2(l0, l1);
                }
            }
    }
    #pragma unroll
    for (int mr = 0; mr < 2; mr++)
        #pragma unroll
        for (int nc = 0; nc < 4; nc++)
            #pragma unroll
            for (int e = 0; e < 4; e++) { accA[mr][nc][e] = 0.f; accB[mr][nc][e] = 0.f; }

    // phase 2: K=128 in 4 chunks of 32
    for (int c2 = 0; c2 < 4; c2++) {
        __syncthreads();
        stage_w(8 + (c2 >> 1), 10 + (c2 >> 1), c2 & 1);
        CP_COMMIT(); CP_WAIT0();
        __syncthreads();
        mma_chunk(SM_P + c2 * 64, P_STR, P_PLANE);
    }

    // epilogue 2
    {
        const float* bSp = (const float*)(smem + SM_BS);
        const float* bRp = (const float*)(smem + SM_BR);
        #pragma unroll
        for (int mr = 0; mr < 2; mr++)
            #pragma unroll
            for (int nc = 0; nc < 4; nc++) {
                int m = m0 + mr * 16 + gr, n = n0 + nc * 8 + cl * 2;
                #pragma unroll
                for (int h = 0; h < 2; h++) {
                    size_t gi = (size_t)(t0 + m + h * 8) * RC + n;
                    float2 rold = *(const float2*)&rin[gi];
                    float2 rnew;
                    rnew.x = rold.x + accB[mr][nc][h * 2 + 0] + bRp[n];
                    rnew.y = rold.y + accB[mr][nc][h * 2 + 1] + bRp[n + 1];
                    *(float2*)&rout[gi] = rnew;
                    float2 s;
                    s.x = accA[mr][nc][h * 2 + 0] + bSp[n];
                    s.y = accA[mr][nc][h * 2 + 1] + bSp[n + 1];
                    if (!first) {
                        float2 o = *(const float2*)&oacc[gi];
                        s.x += o.x; s.y += o.y;
                    }
                    *(float2*)&oacc[gi] = s;
                }
            }
    }
}

// ---------------- fused skip stack (unchanged) ----------------
#define SK_W0   0
#define SK_WR   4096
#define SK_WF   35840
#define SK_B0   44032
#define SK_BR   44064
#define SK_BF   45056
#define SK_TOT  45312

__global__ __launch_bounds__(512)
void k_skip(const float* __restrict__ oacc,
            const float* __restrict__ w0, const float* __restrict__ b0,
            const float* __restrict__ wr, const float* __restrict__ br,
            const float* __restrict__ wf, const float* __restrict__ bf,
            float* __restrict__ y)
{
    extern __shared__ float sm[];
    const int tid = threadIdx.x;
    for (int i = tid; i < 4096;  i += 512) sm[SK_W0 + i] = w0[i];
    for (int i = tid; i < 31744; i += 512) sm[SK_WR + i] = wr[i];
    for (int i = tid; i < 8192;  i += 512) sm[SK_WF + i] = wf[i];
    for (int i = tid; i < 32;    i += 512) sm[SK_B0 + i] = b0[i];
    for (int i = tid; i < 992;   i += 512) sm[SK_BR + i] = br[i];
    for (int i = tid; i < 256;   i += 512) sm[SK_BF + i] = bf[i];
    __syncthreads();

    const int row = blockIdx.x * 512 + tid;
    float h[32];
    #pragma unroll
    for (int c = 0; c < 32; c++) h[c] = sm[SK_B0 + c];

    const float4* in4 = (const float4*)(oacc + (size_t)row * RC);
    const float4* w0_4 = (const float4*)(sm + SK_W0);
    #pragma unroll 4
    for (int k4 = 0; k4 < 32; k4++) {
        float4 x = __ldg(&in4[k4]);
        x.x = fmaxf(x.x, 0.f); x.y = fmaxf(x.y, 0.f);
        x.z = fmaxf(x.z, 0.f); x.w = fmaxf(x.w, 0.f);
        #pragma unroll
        for (int j = 0; j < 4; j++) {
            float xv = comp(x, j);
            #pragma unroll
            for (int c4 = 0; c4 < 8; c4++) {
                float4 w = w0_4[(k4 * 4 + j) * 8 + c4];
                h[c4*4+0] += xv * w.x; h[c4*4+1] += xv * w.y;
                h[c4*4+2] += xv * w.z; h[c4*4+3] += xv * w.w;
            }
        }
    }
    #pragma unroll 1
    for (int step = 0; step < 31; step++) {
        float hn[32];
        #pragma unroll
        for (int c = 0; c < 32; c++) hn[c] = sm[SK_BR + step * 32 + c];
        const float4* wr4 = (const float4*)(sm + SK_WR + step * 1024);
        #pragma unroll
        for (int k = 0; k < 32; k++) {
            float xv = fmaxf(h[k], 0.f);
            #pragma unroll
            for (int c4 = 0; c4 < 8; c4++) {
                float4 w = wr4[k * 8 + c4];
                hn[c4*4+0] += xv * w.x; hn[c4*4+1] += xv * w.y;
                hn[c4*4+2] += xv * w.z; hn[c4*4+3] += xv * w.w;
            }
        }
        #pragma unroll
        for (int c = 0; c < 32; c++) h[c] = hn[c];
    }
    float rh[32];
    #pragma unroll
    for (int k = 0; k < 32; k++) rh[k] = fmaxf(h[k], 0.f);
    const float4* wf4 = (const float4*)(sm + SK_WF);
    const float4* bf4 = (const float4*)(sm + SK_BF);
    float* yrow = y + (size_t)row * 256;
    #pragma unroll 1
    for (int g = 0; g < 8; g++) {
        float4 acc[8];
        #pragma unroll
        for (int c4 = 0; c4 < 8; c4++) acc[c4] = bf4[g * 8 + c4];
        #pragma unroll
        for (int k = 0; k < 32; k++) {
            float xv = rh[k];
            #pragma unroll
            for (int c4 = 0; c4 < 8; c4++) {
                float4 w = wf4[k * 64 + g * 8 + c4];
                acc[c4].x += xv * w.x; acc[c4].y += xv * w.y;
                acc[c4].z += xv * w.z; acc[c4].w += xv * w.w;
            }
        }
        #pragma unroll
        for (int c4 = 0; c4 < 8; c4++)
            *(float4*)&yrow[g * 32 + c4 * 4] = acc[c4];
    }
}

// ---------------- launch ----------------
extern "C" void kernel_launch(void* const* d_in, const int* in_sizes, int n_in,
                              void* d_out, int out_size)
{
    const float* X      = (const float*)d_in[0];
    const float* init_w = (const float*)d_in[1];
    const float* init_b = (const float*)d_in[2];
    const float* f_w    = (const float*)d_in[3];
    const float* f_b    = (const float*)d_in[4];
    const float* g_w    = (const float*)d_in[5];
    const float* g_b    = (const float*)d_in[6];
    const float* skip_w = (const float*)d_in[7];
    const float* skip_b = (const float*)d_in[8];
    const float* res_w  = (const float*)d_in[9];
    const float* res_b  = (const float*)d_in[10];
    const float* sk0_w  = (const float*)d_in[11];
    const float* sk0_b  = (const float*)d_in[12];
    const float* skr_w  = (const float*)d_in[13];
    const float* skr_b  = (const float*)d_in[14];
    const float* fin_w  = (const float*)d_in[15];
    const float* fin_b  = (const float*)d_in[16];

    float *r0, *r1, *oa;
    __nv_bfloat16* wpre;
    cudaGetSymbolAddress((void**)&r0, g_res0);
    cudaGetSymbolAddress((void**)&r1, g_res1);
    cudaGetSymbolAddress((void**)&oa, g_skipacc);
    cudaGetSymbolAddress((void**)&wpre, g_wprep);

    const int SM_SKIP  = SK_TOT * 4;                   // 181248
    cudaFuncSetAttribute(k_init_mma,  cudaFuncAttributeMaxDynamicSharedMemorySize, SI_TOTAL);
    cudaFuncSetAttribute(k_layer_mma, cudaFuncAttributeMaxDynamicSharedMemorySize, SM_TOTAL);
    cudaFuncSetAttribute(k_skip,      cudaFuncAttributeMaxDynamicSharedMemorySize, SM_SKIP);

    k_prep<<<NLAYERS * 12, 256>>>(f_w, g_w, skip_w, res_w);
    k_prep_init<<<32, 256>>>(init_w);
    k_init_mma<<<M_ROWS / 64, 256, SI_TOTAL>>>(X, init_b, r0);

    const float* rin = r0;
    float* rout = r1;
    for (int i = 0; i < NLAYERS; i++) {
        k_layer_mma<<<M_ROWS / 64, 256, SM_TOTAL>>>(
            rin, rout,
            wpre + (size_t)i * 12 * 2 * 8192,
            f_b + (size_t)i * RC, g_b + (size_t)i * RC,
            skip_b + (size_t)i * RC, res_b + (size_t)i * RC,
            oa, H_DIL[i], (i == 0) ? 1 : 0);
        const float* t = rin; rin = rout; rout = (float*)t;
    }

    k_skip<<<M_ROWS / 512, 512, SM_SKIP>>>(oa, sk0_w, sk0_b, skr_w, skr_b,
                                           fin_w, fin_b, (float*)d_out);
}